// round 7
// baseline (speedup 1.0000x reference)
#include <cuda_runtime.h>
#include <cstddef>

// GazeLSTM on GB300 (sm_103a). B=16384, T=128, half=64.
// Kernel 1: rotation chains only (even blocks backward, odd forward),
//   64 thr = 64 b's, C=8 matrices/chunk, 3-stage cp.async pipeline
//   (two chunks in flight), coalesced writeback via smem.
// Kernel 2: LSTM only, 128 thr = 128 b's, reads back-chain rows 0..63 from
//   out (coalesced, double-buffered), 65 serial steps, writes row 64.
//   Weights loaded once via volatile (no remat), kept in registers.

#define BT  64      // chains: b's per block
#define C   8       // matrices per chunk
#define NQ  18      // float4 per b per chunk
#define LBT 128     // lstm: b's per block
#define LS  8       // lstm steps per chunk
#define LQ  6       // float4 per b per lstm chunk

__device__ __forceinline__ unsigned long long pk2(float lo, float hi) {
    unsigned long long r; asm("mov.b64 %0, {%1, %2};" : "=l"(r) : "f"(lo), "f"(hi)); return r;
}
__device__ __forceinline__ void upk2(float& lo, float& hi, unsigned long long v) {
    asm("mov.b64 {%0, %1}, %2;" : "=f"(lo), "=f"(hi) : "l"(v));
}
__device__ __forceinline__ unsigned long long fma2(unsigned long long a, unsigned long long b, unsigned long long c) {
    unsigned long long d; asm("fma.rn.f32x2 %0, %1, %2, %3;" : "=l"(d) : "l"(a), "l"(b), "l"(c)); return d;
}
__device__ __forceinline__ float tanhx(float x) {
    float y; asm("tanh.approx.f32 %0, %1;" : "=f"(y) : "f"(x)); return y;
}

#define CP16(dst_u32, src_ptr) \
    asm volatile("cp.async.cg.shared.global [%0], [%1], 16;" :: "r"(dst_u32), "l"(src_ptr))
#define CP_COMMIT() asm volatile("cp.async.commit_group;")
#define CP_WAIT2()  asm volatile("cp.async.wait_group 2;")
#define CP_WAIT1()  asm volatile("cp.async.wait_group 1;")
#define CP_WAIT0()  asm volatile("cp.async.wait_group 0;")

// ------------------------- Kernel 1: chains -------------------------

// Stage one chunk: 64 b's x NQ quads, 18 CP16/thread. j0 % 4 == 0 required.
__device__ __forceinline__ void stage_chunk(float4* __restrict__ sdst,
                                            const float4* __restrict__ src4base,
                                            int t9q, int tid) {
    int bp = tid / NQ;
    int q  = tid - bp * NQ;
#pragma unroll
    for (int k = 0; k < NQ; k++) {
        const float4* src = src4base + (size_t)bp * t9q + q;
        unsigned dst = (unsigned)__cvta_generic_to_shared(sdst + q * BT + (bp ^ q));
        CP16(dst, src);
        bp += 3; q += 10;                 // advance 64 = 3*18 + 10
        if (q >= NQ) { q -= NQ; bp += 1; }
    }
}

template <int M>
__device__ __forceinline__ void loadA(float* A, const float4* __restrict__ buf, int tid) {
    constexpr int F0 = 9 * M, QA = F0 >> 2, OFF = F0 & 3;
    float tmp[12];
    *(float4*)(tmp + 0) = buf[(QA + 0) * BT + (tid ^ (QA + 0))];
    *(float4*)(tmp + 4) = buf[(QA + 1) * BT + (tid ^ (QA + 1))];
    *(float4*)(tmp + 8) = buf[(QA + 2) * BT + (tid ^ (QA + 2))];
#pragma unroll
    for (int i = 0; i < 9; i++) A[i] = tmp[OFF + i];
}

// Coalesced writeback: NF floats/b for 64 b's from swizzled sout.
template <int NF>
__device__ __forceinline__ void store_chunk(float* __restrict__ gdst, size_t T3,
                                            const float* __restrict__ sout, int tid) {
    int bp = tid / NF;
    int e  = tid - bp * NF;
    constexpr int DB = BT / NF;
    constexpr int DE = BT % NF;
#pragma unroll
    for (int k = 0; k < NF; k++) {
        gdst[(size_t)bp * T3 + e] = sout[e * BT + (bp ^ e)];
        bp += DB; e += DE;
        if (e >= NF) { e -= NF; bp += 1; }
    }
}

__global__ __launch_bounds__(BT) void chains_kernel(
    const float* __restrict__ dir,   // [B,3]
    const float* __restrict__ R,     // [B,T,3,3]
    float* __restrict__ out,         // [B,T,3]
    int B, int T)
{
    extern __shared__ char smem[];
    float4* sb[3] = { (float4*)smem,
                      (float4*)(smem + 18432),
                      (float4*)(smem + 36864) };
    float* sout = (float*)(smem + 55296);   // 24*64 floats = 6144 B

    const int half = T >> 1;
    const int t9q = (T * 9) >> 2;
    const size_t T3 = (size_t)T * 3;
    const int tid = threadIdx.x;
    const int gb = blockIdx.x;
    const bool is_back = ((gb & 1) == 0);
    const int bbase = (gb >> 1) * BT;
    const int nchunks = half / C;            // 8

    float v0 = __ldg(dir + (size_t)(bbase + tid) * 3 + 0);
    float v1 = __ldg(dir + (size_t)(bbase + tid) * 3 + 1);
    float v2 = __ldg(dir + (size_t)(bbase + tid) * 3 + 2);

    const float4* R4 = (const float4*)R + (size_t)bbase * t9q;
    float* oblk = out + (size_t)bbase * T3;

    if (is_back) {
        // chunk k holds matrices [half-C(k+1), half-Ck), consumed in reverse
        stage_chunk(sb[0], R4 + (((half - C) * 9) >> 2), t9q, tid);         CP_COMMIT();
        stage_chunk(sb[1], R4 + (((half - 2 * C) * 9) >> 2), t9q, tid);     CP_COMMIT();

        for (int cc = 0; cc < nchunks; cc++) {
            if (cc + 2 < nchunks) {
                stage_chunk(sb[(cc + 2) % 3], R4 + (((half - C * (cc + 3)) * 9) >> 2), t9q, tid);
                CP_COMMIT(); CP_WAIT2();
            } else if (cc + 1 < nchunks) CP_WAIT1();
            else CP_WAIT0();
            __syncthreads();

            const float4* buf = sb[cc % 3];
#pragma unroll
            for (int s = 0; s < C; s++) {
                float A[9];
                switch (s) {   // matrix slot 7-s (reverse within chunk)
                    case 0: loadA<7>(A, buf, tid); break;
                    case 1: loadA<6>(A, buf, tid); break;
                    case 2: loadA<5>(A, buf, tid); break;
                    case 3: loadA<4>(A, buf, tid); break;
                    case 4: loadA<3>(A, buf, tid); break;
                    case 5: loadA<2>(A, buf, tid); break;
                    case 6: loadA<1>(A, buf, tid); break;
                    default: loadA<0>(A, buf, tid); break;
                }
                // v = A^T v
                float n0 = fmaf(A[6], v2, fmaf(A[3], v1, A[0] * v0));
                float n1 = fmaf(A[7], v2, fmaf(A[4], v1, A[1] * v0));
                float n2 = fmaf(A[8], v2, fmaf(A[5], v1, A[2] * v0));
                v0 = n0; v1 = n1; v2 = n2;
                const int eo = 3 * s;
                sout[(eo + 0) * BT + (tid ^ (eo + 0))] = v0;
                sout[(eo + 1) * BT + (tid ^ (eo + 1))] = v1;
                sout[(eo + 2) * BT + (tid ^ (eo + 2))] = v2;
            }
            __syncthreads();
            store_chunk<3 * C>(oblk + (size_t)(C * cc) * 3, T3, sout, tid);
        }
    } else {
        // forward: step k uses R[half+k], writes row half+1+k, k = 0..T-2-half
        const int nsteps = T - 1 - half;   // 63
        stage_chunk(sb[0], R4 + ((half * 9) >> 2), t9q, tid);               CP_COMMIT();
        stage_chunk(sb[1], R4 + (((half + C) * 9) >> 2), t9q, tid);         CP_COMMIT();

        for (int cc = 0; cc < nchunks; cc++) {
            if (cc + 2 < nchunks) {
                stage_chunk(sb[(cc + 2) % 3], R4 + (((half + C * (cc + 2)) * 9) >> 2), t9q, tid);
                CP_COMMIT(); CP_WAIT2();
            } else if (cc + 1 < nchunks) CP_WAIT1();
            else CP_WAIT0();
            __syncthreads();

            const float4* buf = sb[cc % 3];
            const int ns = (nsteps - C * cc) < C ? (nsteps - C * cc) : C;
#pragma unroll
            for (int s = 0; s < C; s++) {
                if (s < ns) {
                    float A[9];
                    switch (s) {
                        case 0: loadA<0>(A, buf, tid); break;
                        case 1: loadA<1>(A, buf, tid); break;
                        case 2: loadA<2>(A, buf, tid); break;
                        case 3: loadA<3>(A, buf, tid); break;
                        case 4: loadA<4>(A, buf, tid); break;
                        case 5: loadA<5>(A, buf, tid); break;
                        case 6: loadA<6>(A, buf, tid); break;
                        default: loadA<7>(A, buf, tid); break;
                    }
                    // v = A v
                    float n0 = fmaf(A[2], v2, fmaf(A[1], v1, A[0] * v0));
                    float n1 = fmaf(A[5], v2, fmaf(A[4], v1, A[3] * v0));
                    float n2 = fmaf(A[8], v2, fmaf(A[7], v1, A[6] * v0));
                    v0 = n0; v1 = n1; v2 = n2;
                    const int eo = 3 * s;
                    sout[(eo + 0) * BT + (tid ^ (eo + 0))] = v0;
                    sout[(eo + 1) * BT + (tid ^ (eo + 1))] = v1;
                    sout[(eo + 2) * BT + (tid ^ (eo + 2))] = v2;
                }
            }
            __syncthreads();
            float* gdst = oblk + (size_t)(half + 1 + C * cc) * 3;
            if (ns == C) store_chunk<3 * C>(gdst, T3, sout, tid);
            else         store_chunk<21>(gdst, T3, sout, tid);   // last: 7 steps
        }
    }
}

// ------------------------- Kernel 2: LSTM -------------------------

// Prescaled packed weights (sigmoid gates x0.5; sig(x)=0.5+0.5*tanh(x/2)).
#define LSTM_STEP(x0, x1, x2)                                                        \
    do {                                                                             \
        unsigned long long xx0 = pk2((x0), (x0)), xx1 = pk2((x1), (x1)), xx2 = pk2((x2), (x2)); \
        unsigned long long hh0 = pk2(h0, h0), hh1 = pk2(h1, h1), hh2 = pk2(h2, h2);  \
        float th[12];                                                                \
        _Pragma("unroll") for (int p = 0; p < 6; p++) {                              \
            unsigned long long xp =                                                  \
                fma2(WI[p][0], xx0, fma2(WI[p][1], xx1, fma2(WI[p][2], xx2, BS[p]))); \
            unsigned long long g =                                                   \
                fma2(WH[p][0], hh0, fma2(WH[p][1], hh1, fma2(WH[p][2], hh2, xp)));   \
            float a_, b_; upk2(a_, b_, g);                                           \
            th[2 * p] = tanhx(a_); th[2 * p + 1] = tanhx(b_);                        \
        }                                                                            \
        float i0 = fmaf(0.5f, th[0], 0.5f), i1 = fmaf(0.5f, th[1], 0.5f), i2 = fmaf(0.5f, th[2], 0.5f); \
        float f0 = fmaf(0.5f, th[3], 0.5f), f1 = fmaf(0.5f, th[4], 0.5f), f2 = fmaf(0.5f, th[5], 0.5f); \
        float o0 = fmaf(0.5f, th[9], 0.5f), o1 = fmaf(0.5f, th[10], 0.5f), o2 = fmaf(0.5f, th[11], 0.5f); \
        c0 = fmaf(f0, c0, i0 * th[6]);                                               \
        c1 = fmaf(f1, c1, i1 * th[7]);                                               \
        c2 = fmaf(f2, c2, i2 * th[8]);                                               \
        h0 = o0 * tanhx(c0); h1 = o1 * tanhx(c1); h2 = o2 * tanhx(c2);               \
    } while (0)

// Stage LSTM input chunk: 128 b's x LQ quads, 6 CP16/thread.
__device__ __forceinline__ void stage_chunkL(float4* __restrict__ sdst,
                                             const float4* __restrict__ src4base,
                                             int t3q, int tid) {
    int bp = tid / LQ;
    int q  = tid - bp * LQ;
#pragma unroll
    for (int k = 0; k < LQ; k++) {
        const float4* src = src4base + (size_t)bp * t3q + q;
        unsigned dst = (unsigned)__cvta_generic_to_shared(sdst + q * LBT + (bp ^ q));
        CP16(dst, src);
        q += 2; bp += 21;                 // advance 128 = 21*6 + 2
        if (q >= LQ) { q -= LQ; bp += 1; }
    }
}

__global__ __launch_bounds__(LBT, 1) void lstm_kernel(
    const float* __restrict__ dir,
    const float* __restrict__ Wih, const float* __restrict__ Whh,
    const float* __restrict__ bih, const float* __restrict__ bhh,
    float* __restrict__ out,         // rows 0..half-1 already written
    int B, int T)
{
    __shared__ float4 sbuf[2][LQ * LBT];   // 2 x 12 KB

    const int half = T >> 1;
    const int t3q = (T * 3) >> 2;          // 96 quads per b
    const size_t T3 = (size_t)T * 3;
    const int tid = threadIdx.x;
    const int bbase = blockIdx.x * LBT;
    const int nchunks = half / LS;         // 8

    // one-shot volatile weight loads (prevent in-loop remat), prescaled
    unsigned long long WI[6][3], WH[6][3], BS[6];
    {
        const volatile float* vWI = Wih;
        const volatile float* vWH = Whh;
        const volatile float* vbi = bih;
        const volatile float* vbh = bhh;
#pragma unroll
        for (int p = 0; p < 6; p++) {
            const int g0 = 2 * p, g1 = 2 * p + 1;
            const float s0 = (g0 >= 6 && g0 <= 8) ? 1.0f : 0.5f;
            const float s1 = (g1 >= 6 && g1 <= 8) ? 1.0f : 0.5f;
#pragma unroll
            for (int j = 0; j < 3; j++) {
                WI[p][j] = pk2(vWI[g0 * 3 + j] * s0, vWI[g1 * 3 + j] * s1);
                WH[p][j] = pk2(vWH[g0 * 3 + j] * s0, vWH[g1 * 3 + j] * s1);
            }
            BS[p] = pk2((vbi[g0] + vbh[g0]) * s0, (vbi[g1] + vbh[g1]) * s1);
        }
    }

    float h0 = 0.f, h1 = 0.f, h2 = 0.f, c0 = 0.f, c1 = 0.f, c2 = 0.f;

    const float4* O4 = (const float4*)out + (size_t)bbase * t3q;

    stage_chunkL(sbuf[0], O4, t3q, tid);
    CP_COMMIT();

    for (int cc = 0; cc < nchunks; cc++) {
        if (cc + 1 < nchunks) {
            stage_chunkL(sbuf[(cc + 1) & 1], O4 + (cc + 1) * LQ, t3q, tid);
            CP_COMMIT(); CP_WAIT1();
        } else CP_WAIT0();
        __syncthreads();

        const float4* buf = sbuf[cc & 1];
        float x[4 * LQ];
#pragma unroll
        for (int q = 0; q < LQ; q++)
            *(float4*)(x + 4 * q) = buf[q * LBT + (tid ^ q)];

#pragma unroll
        for (int s = 0; s < LS; s++)
            LSTM_STEP(x[3 * s + 0], x[3 * s + 1], x[3 * s + 2]);

        __syncthreads();
    }

    // final step consumes dir; write row t = half
    const float d0 = __ldg(dir + (size_t)(bbase + tid) * 3 + 0);
    const float d1 = __ldg(dir + (size_t)(bbase + tid) * 3 + 1);
    const float d2 = __ldg(dir + (size_t)(bbase + tid) * 3 + 2);
    LSTM_STEP(d0, d1, d2);

    float* ob = out + (size_t)(bbase + tid) * T3 + (size_t)half * 3;
    ob[0] = h0; ob[1] = h1; ob[2] = h2;
}

// ------------------------- launch -------------------------

extern "C" void kernel_launch(void* const* d_in, const int* in_sizes, int n_in,
                              void* d_out, int out_size)
{
    const float* dir = (const float*)d_in[0];
    const float* R   = (const float*)d_in[1];
    const float* Wih = (const float*)d_in[2];
    const float* Whh = (const float*)d_in[3];
    const float* bih = (const float*)d_in[4];
    const float* bhh = (const float*)d_in[5];
    float* out = (float*)d_out;

    const int B = in_sizes[0] / 3;
    const int T = in_sizes[1] / (B * 9);

    static int attr_set = 0;
    if (!attr_set) {
        cudaFuncSetAttribute(chains_kernel, cudaFuncAttributeMaxDynamicSharedMemorySize, 61440);
        attr_set = 1;
    }

    chains_kernel<<<(B / BT) * 2, BT, 61440>>>(dir, R, out, B, T);
    lstm_kernel<<<B / LBT, LBT>>>(dir, Wih, Whh, bih, bhh, out, B, T);
}

// round 8
// speedup vs baseline: 1.5918x; 1.5918x over previous
#include <cuda_runtime.h>
#include <cstddef>

// GazeLSTM on GB300 (sm_103a). B=16384, T=128, half=64.
// Kernel 1: backward chains only (1 warp = 32 b's, C=8 chunk, double-buffered
//   cp.async, warp-synchronous). Writes rows 0..half-1.
// Kernel 2: mixed grid. Blocks [0, nlstm): LSTM (1 warp = 32 b's, reads rows
//   0..half-1 from out, 65 serial steps, writes row half). Blocks [nlstm, ..):
//   forward chains (writes rows half+1..T-1). LSTM serial latency overlaps
//   forward-chain memory traffic.

#define BT  32      // b's per block (one warp)
#define C   8       // matrices per chunk
#define NQ  18      // float4 per b per chain chunk
#define LS  8       // lstm steps per chunk
#define LQ  6       // float4 per b per lstm chunk

__device__ __forceinline__ unsigned long long pk2(float lo, float hi) {
    unsigned long long r; asm("mov.b64 %0, {%1, %2};" : "=l"(r) : "f"(lo), "f"(hi)); return r;
}
__device__ __forceinline__ void upk2(float& lo, float& hi, unsigned long long v) {
    asm("mov.b64 {%0, %1}, %2;" : "=f"(lo), "=f"(hi) : "l"(v));
}
__device__ __forceinline__ unsigned long long fma2(unsigned long long a, unsigned long long b, unsigned long long c) {
    unsigned long long d; asm("fma.rn.f32x2 %0, %1, %2, %3;" : "=l"(d) : "l"(a), "l"(b), "l"(c)); return d;
}
__device__ __forceinline__ float tanhx(float x) {
    float y; asm("tanh.approx.f32 %0, %1;" : "=f"(y) : "f"(x)); return y;
}

#define CP16(dst_u32, src_ptr) \
    asm volatile("cp.async.cg.shared.global [%0], [%1], 16;" :: "r"(dst_u32), "l"(src_ptr))
#define CP_COMMIT() asm volatile("cp.async.commit_group;")
#define CP_WAIT1()  asm volatile("cp.async.wait_group 1;")
#define CP_WAIT0()  asm volatile("cp.async.wait_group 0;")

// ---------------- shared helpers (32-thread warp versions, proven in R5) ----

// Stage chain chunk: 32 b's x NQ quads, 18 CP16/thread. j0 % 4 == 0 required.
__device__ __forceinline__ void stage_chain(float4* __restrict__ sdst,
                                            const float4* __restrict__ src4base,
                                            int t9q, int tid) {
    int bp = tid / NQ;
    int q  = tid - bp * NQ;
#pragma unroll
    for (int k = 0; k < NQ; k++) {
        const float4* src = src4base + (size_t)bp * t9q + q;
        unsigned dst = (unsigned)__cvta_generic_to_shared(sdst + q * BT + (bp ^ q));
        CP16(dst, src);
        q += 14; bp += 1;                 // advance 32 = 1*18 + 14
        if (q >= NQ) { q -= NQ; bp += 1; }
    }
}

template <int M>
__device__ __forceinline__ void loadA(float* A, const float4* __restrict__ buf, int tid) {
    constexpr int F0 = 9 * M, QA = F0 >> 2, OFF = F0 & 3;
    float tmp[12];
    *(float4*)(tmp + 0) = buf[(QA + 0) * BT + (tid ^ (QA + 0))];
    *(float4*)(tmp + 4) = buf[(QA + 1) * BT + (tid ^ (QA + 1))];
    *(float4*)(tmp + 8) = buf[(QA + 2) * BT + (tid ^ (QA + 2))];
#pragma unroll
    for (int i = 0; i < 9; i++) A[i] = tmp[OFF + i];
}

// Coalesced writeback: NF floats/b for 32 b's from swizzled sout.
template <int NF>
__device__ __forceinline__ void store_chain(float* __restrict__ gdst, size_t T3,
                                            const float* __restrict__ sout, int tid) {
    int bp = tid / NF;
    int e  = tid - bp * NF;
    constexpr int DB = BT / NF;
    constexpr int DE = BT % NF;
#pragma unroll
    for (int k = 0; k < NF; k++) {
        gdst[(size_t)bp * T3 + e] = sout[e * BT + (bp ^ e)];
        bp += DB; e += DE;
        if (e >= NF) { e -= NF; bp += 1; }
    }
}

// ---------------- Kernel 1: backward chains ----------------

__global__ __launch_bounds__(BT) void back_kernel(
    const float* __restrict__ dir, const float* __restrict__ R,
    float* __restrict__ out, int B, int T)
{
    __shared__ float4 sbuf[2][NQ * BT];   // 2 x 9216 B
    __shared__ float  sout[3 * C * BT];   // 3072 B

    const int half = T >> 1;
    const int t9q = (T * 9) >> 2;
    const size_t T3 = (size_t)T * 3;
    const int tid = threadIdx.x;
    const int bbase = blockIdx.x * BT;
    const int nchunks = half / C;          // 8

    float v0 = __ldg(dir + (size_t)(bbase + tid) * 3 + 0);
    float v1 = __ldg(dir + (size_t)(bbase + tid) * 3 + 1);
    float v2 = __ldg(dir + (size_t)(bbase + tid) * 3 + 2);

    const float4* R4 = (const float4*)R + (size_t)bbase * t9q;
    float* oblk = out + (size_t)bbase * T3;

    stage_chain(sbuf[0], R4 + (((half - C) * 9) >> 2), t9q, tid);
    CP_COMMIT();
    for (int cc = 0; cc < nchunks; cc++) {
        if (cc + 1 < nchunks) {
            stage_chain(sbuf[(cc + 1) & 1], R4 + (((half - C * (cc + 2)) * 9) >> 2), t9q, tid);
            CP_COMMIT(); CP_WAIT1();
        } else CP_WAIT0();
        __syncwarp();

        const float4* buf = sbuf[cc & 1];
#pragma unroll
        for (int s = 0; s < C; s++) {
            float A[9];
            switch (s) {   // matrix slot 7-s (reverse within chunk)
                case 0: loadA<7>(A, buf, tid); break;
                case 1: loadA<6>(A, buf, tid); break;
                case 2: loadA<5>(A, buf, tid); break;
                case 3: loadA<4>(A, buf, tid); break;
                case 4: loadA<3>(A, buf, tid); break;
                case 5: loadA<2>(A, buf, tid); break;
                case 6: loadA<1>(A, buf, tid); break;
                default: loadA<0>(A, buf, tid); break;
            }
            // v = A^T v
            float n0 = fmaf(A[6], v2, fmaf(A[3], v1, A[0] * v0));
            float n1 = fmaf(A[7], v2, fmaf(A[4], v1, A[1] * v0));
            float n2 = fmaf(A[8], v2, fmaf(A[5], v1, A[2] * v0));
            v0 = n0; v1 = n1; v2 = n2;
            const int eo = 3 * s;
            sout[(eo + 0) * BT + (tid ^ (eo + 0))] = v0;
            sout[(eo + 1) * BT + (tid ^ (eo + 1))] = v1;
            sout[(eo + 2) * BT + (tid ^ (eo + 2))] = v2;
        }
        __syncwarp();
        store_chain<3 * C>(oblk + (size_t)(C * cc) * 3, T3, sout, tid);
        __syncwarp();
    }
}

// ---------------- Kernel 2: LSTM blocks + forward-chain blocks ----------------

// Packed f32x2 LSTM step; weights prescaled (sigmoid gates x0.5).
#define LSTM_STEP(x0, x1, x2)                                                        \
    do {                                                                             \
        unsigned long long xx0 = pk2((x0), (x0)), xx1 = pk2((x1), (x1)), xx2 = pk2((x2), (x2)); \
        unsigned long long hh0 = pk2(h0, h0), hh1 = pk2(h1, h1), hh2 = pk2(h2, h2);  \
        float th[12];                                                                \
        _Pragma("unroll") for (int p = 0; p < 6; p++) {                              \
            unsigned long long xp =                                                  \
                fma2(WI[p][0], xx0, fma2(WI[p][1], xx1, fma2(WI[p][2], xx2, BS[p]))); \
            unsigned long long g =                                                   \
                fma2(WH[p][0], hh0, fma2(WH[p][1], hh1, fma2(WH[p][2], hh2, xp)));   \
            float a_, b_; upk2(a_, b_, g);                                           \
            th[2 * p] = tanhx(a_); th[2 * p + 1] = tanhx(b_);                        \
        }                                                                            \
        float i0 = fmaf(0.5f, th[0], 0.5f), i1 = fmaf(0.5f, th[1], 0.5f), i2 = fmaf(0.5f, th[2], 0.5f); \
        float f0 = fmaf(0.5f, th[3], 0.5f), f1 = fmaf(0.5f, th[4], 0.5f), f2 = fmaf(0.5f, th[5], 0.5f); \
        float o0 = fmaf(0.5f, th[9], 0.5f), o1 = fmaf(0.5f, th[10], 0.5f), o2 = fmaf(0.5f, th[11], 0.5f); \
        c0 = fmaf(f0, c0, i0 * th[6]);                                               \
        c1 = fmaf(f1, c1, i1 * th[7]);                                               \
        c2 = fmaf(f2, c2, i2 * th[8]);                                               \
        h0 = o0 * tanhx(c0); h1 = o1 * tanhx(c1); h2 = o2 * tanhx(c2);               \
    } while (0)

// Stage LSTM input chunk: 32 b's x LQ quads, 6 CP16/thread.
__device__ __forceinline__ void stage_lstm(float4* __restrict__ sdst,
                                           const float4* __restrict__ src4base,
                                           int t3q, int tid) {
    int bp = tid / LQ;
    int q  = tid - bp * LQ;
#pragma unroll
    for (int k = 0; k < LQ; k++) {
        const float4* src = src4base + (size_t)bp * t3q + q;
        unsigned dst = (unsigned)__cvta_generic_to_shared(sdst + q * BT + (bp ^ q));
        CP16(dst, src);
        q += 2; bp += 5;                  // advance 32 = 5*6 + 2
        if (q >= LQ) { q -= LQ; bp += 1; }
    }
}

__global__ __launch_bounds__(BT) void mix_kernel(
    const float* __restrict__ dir, const float* __restrict__ R,
    const float* __restrict__ Wih, const float* __restrict__ Whh,
    const float* __restrict__ bih, const float* __restrict__ bhh,
    float* __restrict__ out, int B, int T, int nlstm)
{
    __shared__ float4 sbuf[2][NQ * BT];   // lstm uses first LQ*BT quads of each
    __shared__ float  sout[3 * C * BT];

    const int half = T >> 1;
    const size_t T3 = (size_t)T * 3;
    const int tid = threadIdx.x;

    if ((int)blockIdx.x < nlstm) {
        // ============ LSTM block: 32 b's ============
        const int t3q = (T * 3) >> 2;          // 96 quads per b
        const int bbase = blockIdx.x * BT;
        const int nchunks = half / LS;         // 8

        // packed, prescaled weights (__ldg, non-volatile: R5's fastest variant —
        // ptxas may keep or reload from L1; measured best)
        unsigned long long WI[6][3], WH[6][3], BS[6];
#pragma unroll
        for (int p = 0; p < 6; p++) {
            const int g0 = 2 * p, g1 = 2 * p + 1;
            const float s0 = (g0 >= 6 && g0 <= 8) ? 1.0f : 0.5f;
            const float s1 = (g1 >= 6 && g1 <= 8) ? 1.0f : 0.5f;
#pragma unroll
            for (int j = 0; j < 3; j++) {
                WI[p][j] = pk2(__ldg(Wih + g0 * 3 + j) * s0, __ldg(Wih + g1 * 3 + j) * s1);
                WH[p][j] = pk2(__ldg(Whh + g0 * 3 + j) * s0, __ldg(Whh + g1 * 3 + j) * s1);
            }
            BS[p] = pk2((__ldg(bih + g0) + __ldg(bhh + g0)) * s0,
                        (__ldg(bih + g1) + __ldg(bhh + g1)) * s1);
        }

        float h0 = 0.f, h1 = 0.f, h2 = 0.f, c0 = 0.f, c1 = 0.f, c2 = 0.f;
        const float4* O4 = (const float4*)out + (size_t)bbase * t3q;

        stage_lstm(sbuf[0], O4, t3q, tid);
        CP_COMMIT();

        for (int cc = 0; cc < nchunks; cc++) {
            if (cc + 1 < nchunks) {
                stage_lstm(sbuf[(cc + 1) & 1], O4 + (cc + 1) * LQ, t3q, tid);
                CP_COMMIT(); CP_WAIT1();
            } else CP_WAIT0();
            __syncwarp();

            const float4* buf = sbuf[cc & 1];
            float x[4 * LQ];
#pragma unroll
            for (int q = 0; q < LQ; q++)
                *(float4*)(x + 4 * q) = buf[q * BT + (tid ^ q)];

#pragma unroll
            for (int s = 0; s < LS; s++)
                LSTM_STEP(x[3 * s + 0], x[3 * s + 1], x[3 * s + 2]);

            __syncwarp();
        }

        // final step consumes dir; write row t = half
        const float d0 = __ldg(dir + (size_t)(bbase + tid) * 3 + 0);
        const float d1 = __ldg(dir + (size_t)(bbase + tid) * 3 + 1);
        const float d2 = __ldg(dir + (size_t)(bbase + tid) * 3 + 2);
        LSTM_STEP(d0, d1, d2);

        float* ob = out + (size_t)(bbase + tid) * T3 + (size_t)half * 3;
        ob[0] = h0; ob[1] = h1; ob[2] = h2;
    } else {
        // ============ forward-chain block: 32 b's ============
        const int t9q = (T * 9) >> 2;
        const int bbase = ((int)blockIdx.x - nlstm) * BT;
        const int nchunks = half / C;          // 8
        const int nsteps = T - 1 - half;       // 63

        float v0 = __ldg(dir + (size_t)(bbase + tid) * 3 + 0);
        float v1 = __ldg(dir + (size_t)(bbase + tid) * 3 + 1);
        float v2 = __ldg(dir + (size_t)(bbase + tid) * 3 + 2);

        const float4* R4 = (const float4*)R + (size_t)bbase * t9q;
        float* oblk = out + (size_t)bbase * T3;

        stage_chain(sbuf[0], R4 + ((half * 9) >> 2), t9q, tid);
        CP_COMMIT();
        for (int cc = 0; cc < nchunks; cc++) {
            if (cc + 1 < nchunks) {
                stage_chain(sbuf[(cc + 1) & 1], R4 + (((half + C * (cc + 1)) * 9) >> 2), t9q, tid);
                CP_COMMIT(); CP_WAIT1();
            } else CP_WAIT0();
            __syncwarp();

            const float4* buf = sbuf[cc & 1];
            const int ns = (nsteps - C * cc) < C ? (nsteps - C * cc) : C;
#pragma unroll
            for (int s = 0; s < C; s++) {
                if (s < ns) {
                    float A[9];
                    switch (s) {
                        case 0: loadA<0>(A, buf, tid); break;
                        case 1: loadA<1>(A, buf, tid); break;
                        case 2: loadA<2>(A, buf, tid); break;
                        case 3: loadA<3>(A, buf, tid); break;
                        case 4: loadA<4>(A, buf, tid); break;
                        case 5: loadA<5>(A, buf, tid); break;
                        case 6: loadA<6>(A, buf, tid); break;
                        default: loadA<7>(A, buf, tid); break;
                    }
                    // v = A v
                    float n0 = fmaf(A[2], v2, fmaf(A[1], v1, A[0] * v0));
                    float n1 = fmaf(A[5], v2, fmaf(A[4], v1, A[3] * v0));
                    float n2 = fmaf(A[8], v2, fmaf(A[7], v1, A[6] * v0));
                    v0 = n0; v1 = n1; v2 = n2;
                    const int eo = 3 * s;
                    sout[(eo + 0) * BT + (tid ^ (eo + 0))] = v0;
                    sout[(eo + 1) * BT + (tid ^ (eo + 1))] = v1;
                    sout[(eo + 2) * BT + (tid ^ (eo + 2))] = v2;
                }
            }
            __syncwarp();
            float* gdst = oblk + (size_t)(half + 1 + C * cc) * 3;
            if (ns == C) store_chain<3 * C>(gdst, T3, sout, tid);
            else         store_chain<21>(gdst, T3, sout, tid);   // last: 7 steps
            __syncwarp();
        }
    }
}

// ---------------- launch ----------------

extern "C" void kernel_launch(void* const* d_in, const int* in_sizes, int n_in,
                              void* d_out, int out_size)
{
    const float* dir = (const float*)d_in[0];
    const float* R   = (const float*)d_in[1];
    const float* Wih = (const float*)d_in[2];
    const float* Whh = (const float*)d_in[3];
    const float* bih = (const float*)d_in[4];
    const float* bhh = (const float*)d_in[5];
    float* out = (float*)d_out;

    const int B = in_sizes[0] / 3;
    const int T = in_sizes[1] / (B * 9);
    const int nlstm = B / BT;   // 512
    const int nfwd  = B / BT;   // 512

    back_kernel<<<B / BT, BT>>>(dir, R, out, B, T);
    mix_kernel<<<nlstm + nfwd, BT>>>(dir, R, Wih, Whh, bih, bhh, out, B, T, nlstm);
}

// round 9
// speedup vs baseline: 1.9200x; 1.2062x over previous
#include <cuda_runtime.h>
#include <cstddef>

// GazeLSTM on GB300 (sm_103a). B=16384, T=128, half=64.
// Single kernel, 32-thread (1-warp) blocks:
//  * blocks [0, nback): backward chain + FUSED LSTM. Chain x_t feeds the LSTM
//    directly from registers (t ascending). LSTM weights live in SMEM as
//    packed u64 (LDS.64, broadcast; smem aliasing prevents reg hoist/spill).
//    Writes rows 0..half-1 and row half.
//  * blocks [nback, ..): forward chain (R8-proven path). Writes rows half+1..T-1.

#define BT  32      // b's per block (one warp)
#define C   8       // matrices per chunk
#define NQ  18      // float4 per b per chain chunk

__device__ __forceinline__ unsigned long long pk2(float lo, float hi) {
    unsigned long long r; asm("mov.b64 %0, {%1, %2};" : "=l"(r) : "f"(lo), "f"(hi)); return r;
}
__device__ __forceinline__ void upk2(float& lo, float& hi, unsigned long long v) {
    asm("mov.b64 {%0, %1}, %2;" : "=f"(lo), "=f"(hi) : "l"(v));
}
__device__ __forceinline__ unsigned long long fma2(unsigned long long a, unsigned long long b, unsigned long long c) {
    unsigned long long d; asm("fma.rn.f32x2 %0, %1, %2, %3;" : "=l"(d) : "l"(a), "l"(b), "l"(c)); return d;
}
__device__ __forceinline__ float tanhx(float x) {
    float y; asm("tanh.approx.f32 %0, %1;" : "=f"(y) : "f"(x)); return y;
}

#define CP16(dst_u32, src_ptr) \
    asm volatile("cp.async.cg.shared.global [%0], [%1], 16;" :: "r"(dst_u32), "l"(src_ptr))
#define CP_COMMIT() asm volatile("cp.async.commit_group;")
#define CP_WAIT1()  asm volatile("cp.async.wait_group 1;")
#define CP_WAIT0()  asm volatile("cp.async.wait_group 0;")

// Stage chain chunk: 32 b's x NQ quads, 18 CP16/thread. j0 % 4 == 0 required.
__device__ __forceinline__ void stage_chain(float4* __restrict__ sdst,
                                            const float4* __restrict__ src4base,
                                            int t9q, int tid) {
    int bp = tid / NQ;
    int q  = tid - bp * NQ;
#pragma unroll
    for (int k = 0; k < NQ; k++) {
        const float4* src = src4base + (size_t)bp * t9q + q;
        unsigned dst = (unsigned)__cvta_generic_to_shared(sdst + q * BT + (bp ^ q));
        CP16(dst, src);
        q += 14; bp += 1;                 // advance 32 = 1*18 + 14
        if (q >= NQ) { q -= NQ; bp += 1; }
    }
}

template <int M>
__device__ __forceinline__ void loadA(float* A, const float4* __restrict__ buf, int tid) {
    constexpr int F0 = 9 * M, QA = F0 >> 2, OFF = F0 & 3;
    float tmp[12];
    *(float4*)(tmp + 0) = buf[(QA + 0) * BT + (tid ^ (QA + 0))];
    *(float4*)(tmp + 4) = buf[(QA + 1) * BT + (tid ^ (QA + 1))];
    *(float4*)(tmp + 8) = buf[(QA + 2) * BT + (tid ^ (QA + 2))];
#pragma unroll
    for (int i = 0; i < 9; i++) A[i] = tmp[OFF + i];
}

// Coalesced writeback: NF floats/b for 32 b's from swizzled sout.
template <int NF>
__device__ __forceinline__ void store_chain(float* __restrict__ gdst, size_t T3,
                                            const float* __restrict__ sout, int tid) {
    int bp = tid / NF;
    int e  = tid - bp * NF;
    constexpr int DB = BT / NF;
    constexpr int DE = BT % NF;
#pragma unroll
    for (int k = 0; k < NF; k++) {
        gdst[(size_t)bp * T3 + e] = sout[e * BT + (bp ^ e)];
        bp += DB; e += DE;
        if (e >= NF) { e -= NF; bp += 1; }
    }
}

// LSTM step with SMEM-resident packed weights (prescaled: sigmoid gates x0.5;
// sig(x) = 0.5 + 0.5*tanh(x/2)). swts layout: [p][0..2]=WI, [3..5]=WH, [6]=bias.
#define LSTM_STEP_S(x0, x1, x2)                                                      \
    do {                                                                             \
        unsigned long long xx0 = pk2((x0), (x0)), xx1 = pk2((x1), (x1)), xx2 = pk2((x2), (x2)); \
        unsigned long long hh0 = pk2(h0, h0), hh1 = pk2(h1, h1), hh2 = pk2(h2, h2);  \
        float th[12];                                                                \
        _Pragma("unroll") for (int p = 0; p < 6; p++) {                              \
            const unsigned long long* wp = swts + p * 7;                             \
            unsigned long long xp = fma2(wp[0], xx0, fma2(wp[1], xx1, fma2(wp[2], xx2, wp[6]))); \
            unsigned long long g  = fma2(wp[3], hh0, fma2(wp[4], hh1, fma2(wp[5], hh2, xp)));    \
            float a_, b_; upk2(a_, b_, g);                                           \
            th[2 * p] = tanhx(a_); th[2 * p + 1] = tanhx(b_);                        \
        }                                                                            \
        float i0 = fmaf(0.5f, th[0], 0.5f), i1 = fmaf(0.5f, th[1], 0.5f), i2 = fmaf(0.5f, th[2], 0.5f); \
        float f0 = fmaf(0.5f, th[3], 0.5f), f1 = fmaf(0.5f, th[4], 0.5f), f2 = fmaf(0.5f, th[5], 0.5f); \
        float o0 = fmaf(0.5f, th[9], 0.5f), o1 = fmaf(0.5f, th[10], 0.5f), o2 = fmaf(0.5f, th[11], 0.5f); \
        c0 = fmaf(f0, c0, i0 * th[6]);                                               \
        c1 = fmaf(f1, c1, i1 * th[7]);                                               \
        c2 = fmaf(f2, c2, i2 * th[8]);                                               \
        h0 = o0 * tanhx(c0); h1 = o1 * tanhx(c1); h2 = o2 * tanhx(c2);               \
    } while (0)

__global__ __launch_bounds__(BT) void gaze_kernel(
    const float* __restrict__ dir, const float* __restrict__ R,
    const float* __restrict__ Wih, const float* __restrict__ Whh,
    const float* __restrict__ bih, const float* __restrict__ bhh,
    float* __restrict__ out, int B, int T, int nback)
{
    __shared__ float4 sbuf[2][NQ * BT];           // 2 x 9216 B
    __shared__ float  sout[3 * C * BT];           // 3072 B
    __shared__ unsigned long long swts[42];       // 336 B (fused blocks only)

    const int half = T >> 1;
    const int t9q = (T * 9) >> 2;
    const size_t T3 = (size_t)T * 3;
    const int tid = threadIdx.x;
    const int nchunks = half / C;                 // 8

    if ((int)blockIdx.x < nback) {
        // ============ fused backward chain + LSTM: 32 b's ============
        const int bbase = blockIdx.x * BT;

        // SMEM weight init: 6 threads, one gate-pair row each.
        if (tid < 6) {
            const int p = tid, g0 = 2 * p, g1 = 2 * p + 1;
            const float s0 = (g0 >= 6 && g0 <= 8) ? 1.0f : 0.5f;
            const float s1 = (g1 >= 6 && g1 <= 8) ? 1.0f : 0.5f;
#pragma unroll
            for (int j = 0; j < 3; j++) {
                swts[p * 7 + j]     = pk2(__ldg(Wih + g0 * 3 + j) * s0, __ldg(Wih + g1 * 3 + j) * s1);
                swts[p * 7 + 3 + j] = pk2(__ldg(Whh + g0 * 3 + j) * s0, __ldg(Whh + g1 * 3 + j) * s1);
            }
            swts[p * 7 + 6] = pk2((__ldg(bih + g0) + __ldg(bhh + g0)) * s0,
                                  (__ldg(bih + g1) + __ldg(bhh + g1)) * s1);
        }

        const float d0 = __ldg(dir + (size_t)(bbase + tid) * 3 + 0);
        const float d1 = __ldg(dir + (size_t)(bbase + tid) * 3 + 1);
        const float d2 = __ldg(dir + (size_t)(bbase + tid) * 3 + 2);
        float v0 = d0, v1 = d1, v2 = d2;
        float h0 = 0.f, h1 = 0.f, h2 = 0.f, c0 = 0.f, c1 = 0.f, c2 = 0.f;

        const float4* R4 = (const float4*)R + (size_t)bbase * t9q;
        float* oblk = out + (size_t)bbase * T3;

        stage_chain(sbuf[0], R4 + (((half - C) * 9) >> 2), t9q, tid);
        CP_COMMIT();
        __syncwarp();                              // weights + buffers visible

        for (int cc = 0; cc < nchunks; cc++) {
            if (cc + 1 < nchunks) {
                stage_chain(sbuf[(cc + 1) & 1], R4 + (((half - C * (cc + 2)) * 9) >> 2), t9q, tid);
                CP_COMMIT(); CP_WAIT1();
            } else CP_WAIT0();
            __syncwarp();

            const float4* buf = sbuf[cc & 1];
#pragma unroll
            for (int s = 0; s < C; s++) {
                float A[9];
                switch (s) {   // matrix slot 7-s (reverse within chunk) => t ascending
                    case 0: loadA<7>(A, buf, tid); break;
                    case 1: loadA<6>(A, buf, tid); break;
                    case 2: loadA<5>(A, buf, tid); break;
                    case 3: loadA<4>(A, buf, tid); break;
                    case 4: loadA<3>(A, buf, tid); break;
                    case 5: loadA<2>(A, buf, tid); break;
                    case 6: loadA<1>(A, buf, tid); break;
                    default: loadA<0>(A, buf, tid); break;
                }
                // v = A^T v
                float n0 = fmaf(A[6], v2, fmaf(A[3], v1, A[0] * v0));
                float n1 = fmaf(A[7], v2, fmaf(A[4], v1, A[1] * v0));
                float n2 = fmaf(A[8], v2, fmaf(A[5], v1, A[2] * v0));
                v0 = n0; v1 = n1; v2 = n2;
                const int eo = 3 * s;
                sout[(eo + 0) * BT + (tid ^ (eo + 0))] = v0;
                sout[(eo + 1) * BT + (tid ^ (eo + 1))] = v1;
                sout[(eo + 2) * BT + (tid ^ (eo + 2))] = v2;

                LSTM_STEP_S(v0, v1, v2);           // consumes x_t = dirs[8cc+s]
            }
            __syncwarp();
            store_chain<3 * C>(oblk + (size_t)(C * cc) * 3, T3, sout, tid);
            __syncwarp();
        }

        // final LSTM step consumes dir; h is the output row at t = half
        LSTM_STEP_S(d0, d1, d2);
        float* ob = out + (size_t)(bbase + tid) * T3 + (size_t)half * 3;
        ob[0] = h0; ob[1] = h1; ob[2] = h2;
    } else {
        // ============ forward chain: 32 b's (R8-proven) ============
        const int bbase = ((int)blockIdx.x - nback) * BT;
        const int nsteps = T - 1 - half;           // 63

        float v0 = __ldg(dir + (size_t)(bbase + tid) * 3 + 0);
        float v1 = __ldg(dir + (size_t)(bbase + tid) * 3 + 1);
        float v2 = __ldg(dir + (size_t)(bbase + tid) * 3 + 2);

        const float4* R4 = (const float4*)R + (size_t)bbase * t9q;
        float* oblk = out + (size_t)bbase * T3;

        stage_chain(sbuf[0], R4 + ((half * 9) >> 2), t9q, tid);
        CP_COMMIT();
        for (int cc = 0; cc < nchunks; cc++) {
            if (cc + 1 < nchunks) {
                stage_chain(sbuf[(cc + 1) & 1], R4 + (((half + C * (cc + 1)) * 9) >> 2), t9q, tid);
                CP_COMMIT(); CP_WAIT1();
            } else CP_WAIT0();
            __syncwarp();

            const float4* buf = sbuf[cc & 1];
            const int ns = (nsteps - C * cc) < C ? (nsteps - C * cc) : C;
#pragma unroll
            for (int s = 0; s < C; s++) {
                if (s < ns) {
                    float A[9];
                    switch (s) {
                        case 0: loadA<0>(A, buf, tid); break;
                        case 1: loadA<1>(A, buf, tid); break;
                        case 2: loadA<2>(A, buf, tid); break;
                        case 3: loadA<3>(A, buf, tid); break;
                        case 4: loadA<4>(A, buf, tid); break;
                        case 5: loadA<5>(A, buf, tid); break;
                        case 6: loadA<6>(A, buf, tid); break;
                        default: loadA<7>(A, buf, tid); break;
                    }
                    // v = A v
                    float n0 = fmaf(A[2], v2, fmaf(A[1], v1, A[0] * v0));
                    float n1 = fmaf(A[5], v2, fmaf(A[4], v1, A[3] * v0));
                    float n2 = fmaf(A[8], v2, fmaf(A[7], v1, A[6] * v0));
                    v0 = n0; v1 = n1; v2 = n2;
                    const int eo = 3 * s;
                    sout[(eo + 0) * BT + (tid ^ (eo + 0))] = v0;
                    sout[(eo + 1) * BT + (tid ^ (eo + 1))] = v1;
                    sout[(eo + 2) * BT + (tid ^ (eo + 2))] = v2;
                }
            }
            __syncwarp();
            float* gdst = oblk + (size_t)(half + 1 + C * cc) * 3;
            if (ns == C) store_chain<3 * C>(gdst, T3, sout, tid);
            else         store_chain<21>(gdst, T3, sout, tid);   // last: 7 steps
            __syncwarp();
        }
    }
}

extern "C" void kernel_launch(void* const* d_in, const int* in_sizes, int n_in,
                              void* d_out, int out_size)
{
    const float* dir = (const float*)d_in[0];
    const float* R   = (const float*)d_in[1];
    const float* Wih = (const float*)d_in[2];
    const float* Whh = (const float*)d_in[3];
    const float* bih = (const float*)d_in[4];
    const float* bhh = (const float*)d_in[5];
    float* out = (float*)d_out;

    const int B = in_sizes[0] / 3;
    const int T = in_sizes[1] / (B * 9);
    const int nback = B / BT;   // 512
    const int nfwd  = B / BT;   // 512

    gaze_kernel<<<nback + nfwd, BT>>>(dir, R, Wih, Whh, bih, bhh, out, B, T, nback);
}